// round 8
// baseline (speedup 1.0000x reference)
#include <cuda_runtime.h>
#include <cuda_fp16.h>
#include <cstdint>

#define BB   256
#define TT   256
#define KTOK 128
#define HH   512
#define G4H  2048
#define DD   128

#define NCTA 128
#define NTHR 256

#define BG_PITCH 80u                    // 32 gate cols * 2B + 16B pad (init staging only)
#define BO_PITCH 16u
#define BO_BUF   8192u

#define BG_OFF  0u
#define BO_OFF  40960u                  // 2 buffers x 8192
#define XG_OFF  57344u
#define SMEM_BYTES 57472u

__device__ __half    g_h[2][BB * HH];
__device__ unsigned  g_cnt[2 * 32];     // per-half arrival counters

__global__ void reset_kernel() { if (threadIdx.x < 64) g_cnt[threadIdx.x] = 0u; }

__device__ __forceinline__ uint32_t smem_u32(const void* p) {
    uint32_t a;
    asm("{ .reg .u64 t; cvta.to.shared.u64 t, %1; cvt.u32.u64 %0, t; }" : "=r"(a) : "l"(p));
    return a;
}
__device__ __forceinline__ float tanha(float x) {
    float r; asm("tanh.approx.f32 %0, %1;" : "=f"(r) : "f"(x)); return r;
}
__device__ __forceinline__ float sigm(float x) { return fmaf(0.5f, tanha(0.5f * x), 0.5f); }

__device__ __forceinline__ void ldsm_x4t(uint32_t* r, uint32_t addr) {
    asm volatile("ldmatrix.sync.aligned.m8n8.x4.trans.shared.b16 {%0,%1,%2,%3}, [%4];"
        : "=r"(r[0]), "=r"(r[1]), "=r"(r[2]), "=r"(r[3]) : "r"(addr));
}
__device__ __forceinline__ void ldsm_x2t(uint32_t* r, uint32_t addr) {
    asm volatile("ldmatrix.sync.aligned.m8n8.x2.trans.shared.b16 {%0,%1}, [%2];"
        : "=r"(r[0]), "=r"(r[1]) : "r"(addr));
}
__device__ __forceinline__ void mma16816(float* d, uint32_t a0, uint32_t a1, uint32_t a2,
                                         uint32_t a3, uint32_t b0, uint32_t b1) {
    asm volatile("mma.sync.aligned.m16n8k16.row.col.f32.f16.f16.f32 "
        "{%0,%1,%2,%3}, {%4,%5,%6,%7}, {%8,%9}, {%0,%1,%2,%3};"
        : "+f"(d[0]), "+f"(d[1]), "+f"(d[2]), "+f"(d[3])
        : "r"(a0), "r"(a1), "r"(a2), "r"(a3), "r"(b0), "r"(b1));
}

// k permutation within 32-blocks (R6, proven): direct LDG.128 -> mma A fragments
__device__ __forceinline__ int vk_to_ak(int vk) {
    int kfl = (vk >> 4) & 1, pair = (vk >> 3) & 1, qc = (vk >> 1) & 3, elem = vk & 1;
    return (vk & ~31) + 8 * qc + kfl * 4 + pair * 2 + elem;
}
__device__ __forceinline__ int ak_to_vk(int ak) {
    int qc = (ak >> 3) & 3, j = ak & 7;
    return (ak & ~31) + (j >> 2) * 16 + ((j >> 1) & 1) * 8 + qc * 2 + (j & 1);
}

__global__ void __launch_bounds__(NTHR, 1) lstm_mma_kernel(
    const float* __restrict__ z,     const float* __restrict__ Wz,
    const float* __restrict__ bz,    const float* __restrict__ token,
    const float* __restrict__ Wi,    const float* __restrict__ Wh,
    const float* __restrict__ bh,    const float* __restrict__ Wout,
    const float* __restrict__ bout,  float* __restrict__ out)
{
    extern __shared__ char smem[];
    const uint32_t sb = smem_u32(smem);

    const int tid  = threadIdx.x;
    const int lane = tid & 31;
    const int w    = tid >> 5;
    const int mq   = w & 3;               // rows mq*32 .. +32 (2 m-tiles)
    const int nq   = w >> 2;               // col half: units nq*4..+4
    const int mh   = blockIdx.x & 1;      // batch half (sync domain)
    const int jg   = blockIdx.x >> 1;     // unit group 0..63 (8 units)
    const int m0   = mh * 128;
    const int j0   = jg * 8;

    const int qr   = lane >> 2;
    const int qc   = lane & 3;

    // init-staging ldsm base (col half nq -> +32 bytes)
    const uint32_t bgLane = sb + BG_OFF + (uint32_t)(lane & 15) * BG_PITCH
                          + (uint32_t)(lane >> 4) * 16u + (uint32_t)nq * 32u;
    const uint32_t boLane = sb + BO_OFF + (uint32_t)(lane & 15) * BO_PITCH;

    float* sxg = (float*)(smem + XG_OFF);
    volatile unsigned* myCnt = &g_cnt[mh * 32];

    // ---------------- one-time init ----------------
    for (int i = tid; i < 1024; i += NTHR) ((uint4*)(smem + BO_OFF))[i] = make_uint4(0, 0, 0, 0);

    // stage Wh -> smem, VIRTUAL k row order, unit-interleaved column order:
    // n_new: nq(1b) | n8(1b) | du(1b) | gate(2b);  unit u = nq*4 + n8*2 + du
    for (int idx = tid; idx < 512 * 32; idx += NTHR) {
        int vk = idx >> 5, n = idx & 31;
        int ak = vk_to_ak(vk);
        int gate = n & 3, du = (n >> 2) & 1, n8 = (n >> 3) & 1, nqq = n >> 4;
        int u = nqq * 4 + n8 * 2 + du;
        float v = __ldg(&Wh[(size_t)ak * G4H + gate * HH + j0 + u]);
        *(__half*)(smem + BG_OFF + (uint32_t)vk * BG_PITCH + (uint32_t)n * 2u) = __float2half_rn(v);
    }
    if (tid < 32) {
        int col = (tid >> 3) * HH + j0 + (tid & 7);
        float s = bh[col];
        #pragma unroll 4
        for (int k = 0; k < KTOK; ++k)
            s = fmaf(token[k], __ldg(&Wi[(size_t)k * G4H + col]), s);
        sxg[tid] = s;   // sxg[gate*8 + u]
    }
    {   // h0 = relu(z @ Wz + bz)
        const int r  = tid >> 1;
        const int ub = (tid & 1) * 4;
        float a[4];
        #pragma unroll
        for (int q = 0; q < 4; ++q) a[q] = bz[j0 + ub + q];
        const float* zr = z + (size_t)(m0 + r) * KTOK;
        #pragma unroll 4
        for (int k = 0; k < KTOK; ++k) {
            float zv = __ldg(zr + k);
            float4 w4 = __ldg((const float4*)&Wz[(size_t)k * HH + j0 + ub]);
            a[0] = fmaf(zv, w4.x, a[0]); a[1] = fmaf(zv, w4.y, a[1]);
            a[2] = fmaf(zv, w4.z, a[2]); a[3] = fmaf(zv, w4.w, a[3]);
        }
        __half2* hp = (__half2*)&g_h[0][(size_t)(m0 + r) * HH + j0 + ub];
        hp[0] = __floats2half2_rn(fmaxf(a[0], 0.f), fmaxf(a[1], 0.f));
        hp[1] = __floats2half2_rn(fmaxf(a[2], 0.f), fmaxf(a[3], 0.f));
    }
    __syncthreads();

    // B-gate fragments -> registers, held for the whole sequence (16 cols x 512 k)
    uint32_t bg[32][4];
    #pragma unroll
    for (int ks = 0; ks < 32; ++ks)
        ldsm_x4t(bg[ks], bgLane + (uint32_t)(ks * 16) * BG_PITCH);

    // initial barrier (ep = 1)
    unsigned ep = 1;
    __syncthreads();
    if (tid == 0) {
        __threadfence();
        asm volatile("red.global.add.u32 [%0], %1;" :: "l"((unsigned*)myCnt), "r"(1u) : "memory");
        while (*myCnt < ep * 64u) {}
        __threadfence();
    }
    __syncthreads();
    ++ep;

    float c8[8];
    #pragma unroll
    for (int e = 0; e < 8; ++e) c8[e] = 0.f;
    float2 wo0, wo1;

    // ---------------- sequential loop ----------------
    #pragma unroll 1
    for (int t = 0; t <= TT; ++t) {
        const __half* hsrc = g_h[t & 1];
        const int te = t - 1;

        const __half* aBase = hsrc + (size_t)(m0 + mq * 32 + qr) * HH + 8 * qc;
        const uint32_t boSel = boLane + (uint32_t)(t & 1) * BO_BUF;

        // prefetch Wout_t for next iteration
        if (t < TT) {
            const float* Wo = Wout + (size_t)t * HH * DD + jg * 2;
            wo0 = __ldcg((const float2*)(Wo + (size_t)(tid * 2) * DD));
            wo1 = __ldcg((const float2*)(Wo + (size_t)(tid * 2 + 1) * DD));
        }

        float acc[2][2][4];   // [mtile][ntile][frag]
        float accO[2][4];
        #pragma unroll
        for (int m = 0; m < 2; ++m)
            #pragma unroll
            for (int n = 0; n < 2; ++n)
                #pragma unroll
                for (int e = 0; e < 4; ++e) acc[m][n][e] = 0.f;
        #pragma unroll
        for (int m = 0; m < 2; ++m)
            #pragma unroll
            for (int e = 0; e < 4; ++e) accO[m][e] = 0.f;

        // A: 4 row-streams (qr, +8, +16, +24), 2-deep ring over 16 k-blocks
        uint4 r[4][2];
        #pragma unroll
        for (int p = 0; p < 2; ++p)
            #pragma unroll
            for (int s = 0; s < 4; ++s)
                r[s][p] = __ldcg((const uint4*)(aBase + (size_t)s * 8 * HH + p * 32));

        uint32_t bo[2][2];
        if (nq == 1) ldsm_x2t(bo[0], boSel);

        #pragma unroll
        for (int b = 0; b < 16; ++b) {
            const int slot = b & 1;
            const uint4 va = r[0][slot], vb = r[1][slot], vc = r[2][slot], vd = r[3][slot];
            if (b + 2 < 16) {
                #pragma unroll
                for (int s = 0; s < 4; ++s)
                    r[s][slot] = __ldcg((const uint4*)(aBase + (size_t)s * 8 * HH + (b + 2) * 32));
            }
            #pragma unroll
            for (int kfl = 0; kfl < 2; ++kfl) {
                const int ks = b * 2 + kfl;
                if (nq == 1 && ks + 1 < 32)
                    ldsm_x2t(bo[(ks + 1) & 1], boSel + (uint32_t)((ks + 1) * 16) * BO_PITCH);
                const uint32_t a0 = kfl ? va.z : va.x, a1 = kfl ? vb.z : vb.x;
                const uint32_t a2 = kfl ? va.w : va.y, a3 = kfl ? vb.w : vb.y;
                const uint32_t a4 = kfl ? vc.z : vc.x, a5 = kfl ? vd.z : vd.x;
                const uint32_t a6 = kfl ? vc.w : vc.y, a7 = kfl ? vd.w : vd.y;
                mma16816(acc[0][0], a0, a1, a2, a3, bg[ks][0], bg[ks][1]);
                mma16816(acc[0][1], a0, a1, a2, a3, bg[ks][2], bg[ks][3]);
                mma16816(acc[1][0], a4, a5, a6, a7, bg[ks][0], bg[ks][1]);
                mma16816(acc[1][1], a4, a5, a6, a7, bg[ks][2], bg[ks][3]);
                if (nq == 1) {
                    mma16816(accO[0], a0, a1, a2, a3, bo[ks & 1][0], bo[ks & 1][1]);
                    mma16816(accO[1], a4, a5, a6, a7, bo[ks & 1][0], bo[ks & 1][1]);
                }
            }
        }

        // ---- critical path: cell update (shfl exchange, no smem) + h store ----
        if (t < TT) {
            __half* hdst = &g_h[(t + 1) & 1][0];
            const int ubase = nq * 4 + (qc >> 1);       // unit for even lanes (per ntile +2n)
            float hv[2][2][2];                           // [m][n][r]
            #pragma unroll
            for (int m = 0; m < 2; ++m) {
                #pragma unroll
                for (int n = 0; n < 2; ++n) {
                    float o0 = __shfl_xor_sync(0xffffffffu, acc[m][n][0], 1);
                    float o1 = __shfl_xor_sync(0xffffffffu, acc[m][n][1], 1);
                    float o2 = __shfl_xor_sync(0xffffffffu, acc[m][n][2], 1);
                    float o3 = __shfl_xor_sync(0xffffffffu, acc[m][n][3], 1);
                    const int u = ubase + n * 2;         // valid on even lanes
                    const float xi = sxg[u], xf = sxg[8 + u], xg = sxg[16 + u], xo = sxg[24 + u];
                    #pragma unroll
                    for (int rr = 0; rr < 2; ++rr) {
                        float gi = sigm (acc[m][n][2 * rr]     + xi);
                        float gf = sigm (acc[m][n][2 * rr + 1] + xf);
                        float gg = tanha((rr ? o2 : o0) + xg);
                        float go = sigm ((rr ? o3 : o1) + xo);
                        const int ci = m * 4 + n * 2 + rr;
                        float cv = gf * c8[ci] + gi * gg;
                        c8[ci] = cv;
                        hv[m][n][rr] = go * tanha(cv);
                    }
                }
            }
            // pair adjacent units across qc0<->qc2, store half2
            #pragma unroll
            for (int m = 0; m < 2; ++m)
                #pragma unroll
                for (int rr = 0; rr < 2; ++rr) {
                    float p0 = __shfl_xor_sync(0xffffffffu, hv[m][0][rr], 2);
                    float p1 = __shfl_xor_sync(0xffffffffu, hv[m][1][rr], 2);
                    const int row = m0 + mq * 32 + qr + m * 16 + rr * 8;
                    if (qc == 0)
                        __stcg((__half2*)&hdst[(size_t)row * HH + j0 + nq * 4],
                               __floats2half2_rn(hv[m][0][rr], p0));
                    else if (qc == 2)
                        __stcg((__half2*)&hdst[(size_t)row * HH + j0 + nq * 4 + 2],
                               __floats2half2_rn(p1, hv[m][1][rr]));
                }
        }

        // ---- barrier arrive ----
        __syncthreads();
        if (t < TT && tid == 0) {
            __threadfence();
            asm volatile("red.global.add.u32 [%0], %1;" :: "l"((unsigned*)myCnt), "r"(1u) : "memory");
        }

        // ---- shadow work: out store + next BO staging ----
        if (t >= 1 && nq == 1 && qc == 0) {
            const float2 bo2 = *(const float2*)&bout[te * DD + jg * 2];
            #pragma unroll
            for (int m = 0; m < 2; ++m)
                #pragma unroll
                for (int rr = 0; rr < 2; ++rr) {
                    const int row = m0 + mq * 32 + qr + m * 16 + rr * 8;
                    *(float2*)&out[(size_t)row * TT * DD + (size_t)te * DD + jg * 2] =
                        make_float2(accO[m][2 * rr] + bo2.x, accO[m][2 * rr + 1] + bo2.y);
                }
        }
        if (t < TT) {
            const uint32_t boNext = BO_OFF + (uint32_t)((t + 1) & 1) * BO_BUF;
            __half2 p0 = __floats2half2_rn(wo0.x, wo0.y);
            __half2 p1 = __floats2half2_rn(wo1.x, wo1.y);
            *(uint32_t*)(smem + boNext + (uint32_t)ak_to_vk(tid * 2) * BO_PITCH)     = *(uint32_t*)&p0;
            *(uint32_t*)(smem + boNext + (uint32_t)ak_to_vk(tid * 2 + 1) * BO_PITCH) = *(uint32_t*)&p1;
        }

        // ---- barrier wait ----
        if (t < TT) {
            if (tid == 0) {
                while (*myCnt < ep * 64u) {}
                __threadfence();
            }
            __syncthreads();
            ++ep;
        }
    }
}

extern "C" void kernel_launch(void* const* d_in, const int* in_sizes, int n_in,
                              void* d_out, int out_size) {
    const float* z     = (const float*)d_in[0];
    const float* Wz    = (const float*)d_in[1];
    const float* bz    = (const float*)d_in[2];
    const float* token = (const float*)d_in[3];
    const float* Wi    = (const float*)d_in[4];
    const float* Wh    = (const float*)d_in[5];
    const float* bh    = (const float*)d_in[6];
    const float* Wout  = (const float*)d_in[7];
    const float* bout  = (const float*)d_in[8];
    float* out = (float*)d_out;

    cudaFuncSetAttribute(lstm_mma_kernel, cudaFuncAttributeMaxDynamicSharedMemorySize, SMEM_BYTES);
    reset_kernel<<<1, 64>>>();
    lstm_mma_kernel<<<NCTA, NTHR, SMEM_BYTES>>>(z, Wz, bz, token, Wi, Wh, bh, Wout, bout, out);
}

// round 9
// speedup vs baseline: 1.3759x; 1.3759x over previous
#include <cuda_runtime.h>
#include <cuda_fp16.h>
#include <cstdint>

#define BB   256
#define TT   256
#define KTOK 128
#define HH   512
#define G4H  2048
#define DD   128

#define NCTA 256
#define NTHR 128

#define BG_PITCH 80u                    // 32 gate cols * 2B + 16B pad
#define BO_PITCH 16u                    // 8 cols (2 real + 6 pad) * 2B
#define BO_BUF   8192u

#define BG_OFF  0u
#define BO_OFF  40960u                  // 2 buffers x 8192
#define XG_OFF  57344u
#define SMEM_BYTES 57472u

__device__ __half    g_h[2][BB * HH];
__device__ unsigned  g_cnt[4 * 32];     // per-quarter arrival counters (128B apart)

__global__ void reset_kernel() { if (threadIdx.x < 128) g_cnt[threadIdx.x] = 0u; }

__device__ __forceinline__ uint32_t smem_u32(const void* p) {
    uint32_t a;
    asm("{ .reg .u64 t; cvta.to.shared.u64 t, %1; cvt.u32.u64 %0, t; }" : "=r"(a) : "l"(p));
    return a;
}
__device__ __forceinline__ float tanha(float x) {
    float r; asm("tanh.approx.f32 %0, %1;" : "=f"(r) : "f"(x)); return r;
}
__device__ __forceinline__ float sigm(float x) { return fmaf(0.5f, tanha(0.5f * x), 0.5f); }

__device__ __forceinline__ void ldsm_x4t(uint32_t* r, uint32_t addr) {
    asm volatile("ldmatrix.sync.aligned.m8n8.x4.trans.shared.b16 {%0,%1,%2,%3}, [%4];"
        : "=r"(r[0]), "=r"(r[1]), "=r"(r[2]), "=r"(r[3]) : "r"(addr));
}
__device__ __forceinline__ void ldsm_x2t(uint32_t* r, uint32_t addr) {
    asm volatile("ldmatrix.sync.aligned.m8n8.x2.trans.shared.b16 {%0,%1}, [%2];"
        : "=r"(r[0]), "=r"(r[1]) : "r"(addr));
}
__device__ __forceinline__ void mma16816(float* d, uint32_t a0, uint32_t a1, uint32_t a2,
                                         uint32_t a3, const uint32_t* b) {
    asm volatile("mma.sync.aligned.m16n8k16.row.col.f32.f16.f16.f32 "
        "{%0,%1,%2,%3}, {%4,%5,%6,%7}, {%8,%9}, {%0,%1,%2,%3};"
        : "+f"(d[0]), "+f"(d[1]), "+f"(d[2]), "+f"(d[3])
        : "r"(a0), "r"(a1), "r"(a2), "r"(a3), "r"(b[0]), "r"(b[1]));
}

// k permutation within 32-blocks (R6, proven): direct LDG.128 -> mma A fragments
__device__ __forceinline__ int vk_to_ak(int vk) {
    int kfl = (vk >> 4) & 1, pair = (vk >> 3) & 1, qc = (vk >> 1) & 3, elem = vk & 1;
    return (vk & ~31) + 8 * qc + kfl * 4 + pair * 2 + elem;
}
__device__ __forceinline__ int ak_to_vk(int ak) {
    int qc = (ak >> 3) & 3, j = ak & 7;
    return (ak & ~31) + (j >> 2) * 16 + ((j >> 1) & 1) * 8 + qc * 2 + (j & 1);
}

__global__ void __launch_bounds__(NTHR, 2) lstm_mma_kernel(
    const float* __restrict__ z,     const float* __restrict__ Wz,
    const float* __restrict__ bz,    const float* __restrict__ token,
    const float* __restrict__ Wi,    const float* __restrict__ Wh,
    const float* __restrict__ bh,    const float* __restrict__ Wout,
    const float* __restrict__ bout,  float* __restrict__ out)
{
    extern __shared__ char smem[];
    const uint32_t sb = smem_u32(smem);

    const int tid  = threadIdx.x;
    const int lane = tid & 31;
    const int w    = tid >> 5;            // warp 0..3 (m-tile within quarter)
    const int mqd  = blockIdx.x >> 6;     // batch quarter = sync domain (0..3)
    const int jg   = blockIdx.x & 63;     // unit group 0..63 (8 units)
    const int m0   = mqd * 64;
    const int j0   = jg * 8;

    const int qr   = lane >> 2;
    const int qc   = lane & 3;
    const int row0 = w * 16 + qr;         // 0..63 within quarter
    const int u0   = qc * 2;

    const uint32_t bgLane = sb + BG_OFF + (uint32_t)(lane & 15) * BG_PITCH
                          + (uint32_t)(lane >> 4) * 16u;
    const uint32_t boLane = sb + BO_OFF + (uint32_t)(lane & 15) * BO_PITCH;

    float* sxg = (float*)(smem + XG_OFF);
    volatile unsigned* myCnt = &g_cnt[mqd * 32];

    // ---------------- one-time init ----------------
    for (int i = tid; i < 1024; i += NTHR) ((uint4*)(smem + BO_OFF))[i] = make_uint4(0, 0, 0, 0);

    // Wh slice -> fp16 smem, VIRTUAL k order
    for (int idx = tid; idx < 512 * 32; idx += NTHR) {
        int vk = idx >> 5, n = idx & 31;
        int ak = vk_to_ak(vk);
        float v = __ldg(&Wh[(size_t)ak * G4H + (n >> 3) * HH + j0 + (n & 7)]);
        *(__half*)(smem + BG_OFF + (uint32_t)vk * BG_PITCH + (uint32_t)n * 2u) = __float2half_rn(v);
    }
    if (tid < 32) {
        int col = (tid >> 3) * HH + j0 + (tid & 7);
        float s = bh[col];
        #pragma unroll 4
        for (int k = 0; k < KTOK; ++k)
            s = fmaf(token[k], __ldg(&Wi[(size_t)k * G4H + col]), s);
        sxg[tid] = s;
    }
    {   // h0 = relu(z @ Wz + bz): thread -> row tid>>1 (0..63), 4 units
        const int r  = tid >> 1;
        const int ub = (tid & 1) * 4;
        float a[4];
        #pragma unroll
        for (int q = 0; q < 4; ++q) a[q] = bz[j0 + ub + q];
        const float* zr = z + (size_t)(m0 + r) * KTOK;
        #pragma unroll 4
        for (int k = 0; k < KTOK; ++k) {
            float zv = __ldg(zr + k);
            float4 w4 = __ldg((const float4*)&Wz[(size_t)k * HH + j0 + ub]);
            a[0] = fmaf(zv, w4.x, a[0]); a[1] = fmaf(zv, w4.y, a[1]);
            a[2] = fmaf(zv, w4.z, a[2]); a[3] = fmaf(zv, w4.w, a[3]);
        }
        __half2* hp = (__half2*)&g_h[0][(size_t)(m0 + r) * HH + j0 + ub];
        hp[0] = __floats2half2_rn(fmaxf(a[0], 0.f), fmaxf(a[1], 0.f));
        hp[1] = __floats2half2_rn(fmaxf(a[2], 0.f), fmaxf(a[3], 0.f));
    }

    // initial counter barrier (ep = 1)
    unsigned ep = 1;
    __syncthreads();
    if (tid == 0) {
        __threadfence();
        asm volatile("red.global.add.u32 [%0], %1;" :: "l"((unsigned*)myCnt), "r"(1u) : "memory");
        while (*myCnt < ep * 64u) {}
        __threadfence();
    }
    __syncthreads();
    ++ep;

    float c4[4] = {0.f, 0.f, 0.f, 0.f};
    float2 wo[4];

    // ---------------- sequential loop ----------------
    #pragma unroll 1
    for (int t = 0; t <= TT; ++t) {
        const __half* hsrc = g_h[t & 1];
        const int te = t - 1;

        const __half* aRow0 = hsrc + (size_t)(m0 + row0) * HH + 8 * qc;
        const __half* aRow8 = aRow0 + 8 * HH;
        const uint32_t boSel = boLane + (uint32_t)(t & 1) * BO_BUF;

        // A-fragment pipeline: 16 blocks of 32 k; 4-deep LDG.128 ring
        uint4 ra[4], rb[4];
        #pragma unroll
        for (int p = 0; p < 4; ++p) {
            ra[p] = __ldcg((const uint4*)(aRow0 + p * 32));
            rb[p] = __ldcg((const uint4*)(aRow8 + p * 32));
        }

        // prefetch Wout_t for next iteration (overlaps mainloop)
        if (t < TT) {
            const float* Wo = Wout + (size_t)t * HH * DD + jg * 2;
            #pragma unroll
            for (int r = 0; r < 4; ++r)
                wo[r] = __ldcg((const float2*)(Wo + (size_t)(tid * 4 + r) * DD));
        }

        float acc[5][4];
        #pragma unroll
        for (int n = 0; n < 5; ++n)
            #pragma unroll
            for (int e = 0; e < 4; ++e) acc[n][e] = 0.f;

        #pragma unroll
        for (int b = 0; b < 16; ++b) {
            const int slot = b & 3;
            const uint4 va = ra[slot], vb = rb[slot];
            if (b + 4 < 16) {
                ra[slot] = __ldcg((const uint4*)(aRow0 + (b + 4) * 32));
                rb[slot] = __ldcg((const uint4*)(aRow8 + (b + 4) * 32));
            }
            #pragma unroll
            for (int kfl = 0; kfl < 2; ++kfl) {
                const uint32_t krow = (uint32_t)(b * 32 + kfl * 16);
                uint32_t b1[4], b2[4], b3[2];
                ldsm_x4t(b1, bgLane + krow * BG_PITCH);
                ldsm_x4t(b2, bgLane + krow * BG_PITCH + 32u);
                ldsm_x2t(b3, boSel + krow * BO_PITCH);
                const uint32_t a0 = kfl ? va.z : va.x;
                const uint32_t a1 = kfl ? vb.z : vb.x;
                const uint32_t a2 = kfl ? va.w : va.y;
                const uint32_t a3 = kfl ? vb.w : vb.y;
                mma16816(acc[0], a0, a1, a2, a3, b1);
                mma16816(acc[1], a0, a1, a2, a3, b1 + 2);
                mma16816(acc[2], a0, a1, a2, a3, b2);
                mma16816(acc[3], a0, a1, a2, a3, b2 + 2);
                mma16816(acc[4], a0, a1, a2, a3, b3);
            }
        }

        // ---- critical path: cell update + h store ----
        if (t < TT) {
            __half* hdst = &g_h[(t + 1) & 1][0];
            float hv[4];
            #pragma unroll
            for (int e = 0; e < 4; ++e) {
                const int u = u0 + (e & 1);
                float gi = sigm (acc[0][e] + sxg[u]);
                float gf = sigm (acc[1][e] + sxg[8 + u]);
                float gg = tanha(acc[2][e] + sxg[16 + u]);
                float go = sigm (acc[3][e] + sxg[24 + u]);
                float cv = gf * c4[e] + gi * gg;
                c4[e] = cv;
                hv[e] = go * tanha(cv);
            }
            __half2 h01 = __floats2half2_rn(hv[0], hv[1]);
            __half2 h23 = __floats2half2_rn(hv[2], hv[3]);
            __stcg((__half2*)&hdst[(size_t)(m0 + row0) * HH + j0 + u0], h01);
            __stcg((__half2*)&hdst[(size_t)(m0 + row0 + 8) * HH + j0 + u0], h23);
        }

        // ---- barrier arrive ----
        __syncthreads();
        if (t < TT && tid == 0) {
            __threadfence();
            asm volatile("red.global.add.u32 [%0], %1;" :: "l"((unsigned*)myCnt), "r"(1u) : "memory");
        }

        // ---- shadow work: out store + next-step BO staging (alternate buffer) ----
        if (t >= 1 && qc == 0) {
            const float2 bo = *(const float2*)&bout[te * DD + jg * 2];
            float2 o0 = make_float2(acc[4][0] + bo.x, acc[4][1] + bo.y);
            float2 o1 = make_float2(acc[4][2] + bo.x, acc[4][3] + bo.y);
            *(float2*)&out[(size_t)(m0 + row0) * TT * DD + (size_t)te * DD + jg * 2] = o0;
            *(float2*)&out[(size_t)(m0 + row0 + 8) * TT * DD + (size_t)te * DD + jg * 2] = o1;
        }
        if (t < TT) {
            const uint32_t boNext = BO_OFF + (uint32_t)((t + 1) & 1) * BO_BUF;
            #pragma unroll
            for (int r = 0; r < 4; ++r) {
                __half2 p = __floats2half2_rn(wo[r].x, wo[r].y);
                *(uint32_t*)(smem + boNext + (uint32_t)ak_to_vk(tid * 4 + r) * BO_PITCH) = *(uint32_t*)&p;
            }
        }

        // ---- barrier wait ----
        if (t < TT) {
            if (tid == 0) {
                while (*myCnt < ep * 64u) {}
                __threadfence();
            }
            __syncthreads();
            ++ep;
        }
    }
}

extern "C" void kernel_launch(void* const* d_in, const int* in_sizes, int n_in,
                              void* d_out, int out_size) {
    const float* z     = (const float*)d_in[0];
    const float* Wz    = (const float*)d_in[1];
    const float* bz    = (const float*)d_in[2];
    const float* token = (const float*)d_in[3];
    const float* Wi    = (const float*)d_in[4];
    const float* Wh    = (const float*)d_in[5];
    const float* bh    = (const float*)d_in[6];
    const float* Wout  = (const float*)d_in[7];
    const float* bout  = (const float*)d_in[8];
    float* out = (float*)d_out;

    cudaFuncSetAttribute(lstm_mma_kernel, cudaFuncAttributeMaxDynamicSharedMemorySize, SMEM_BYTES);
    reset_kernel<<<1, 128>>>();
    lstm_mma_kernel<<<NCTA, NTHR, SMEM_BYTES>>>(z, Wz, bz, token, Wi, Wh, bh, Wout, bout, out);
}